// round 1
// baseline (speedup 1.0000x reference)
#include <cuda_runtime.h>

#define N_USER 50000
#define N_ITEM 50000
#define N_EDGE 600000
#define D 128

// Scratch (allocation-free rule: __device__ globals)
__device__ float4 g_acc_uu[N_USER * (D / 4)];
__device__ float4 g_acc_ub[N_ITEM * (D / 4)];
__device__ float4 g_acc_iu[N_USER * (D / 4)];
__device__ int g_cnt_uu[N_USER];
__device__ int g_cnt_ub[N_ITEM];
__device__ int g_cnt_iu[N_USER];

__global__ void zero_kernel() {
    int i = blockIdx.x * blockDim.x + threadIdx.x;
    float4 z = make_float4(0.f, 0.f, 0.f, 0.f);
    if (i < N_USER * (D / 4)) {
        g_acc_uu[i] = z;
        g_acc_ub[i] = z;
        g_acc_iu[i] = z;
        if (i < N_USER) {
            g_cnt_uu[i] = 0;
            g_cnt_ub[i] = 0;
            g_cnt_iu[i] = 0;
        }
    }
}

// Warp per edge: gather feat[src] (float4/lane) and red.add.v4 into accum[dst].
__global__ void scatter_kernel(const float* __restrict__ fu, const float* __restrict__ fi,
                               const int* __restrict__ suu, const int* __restrict__ duu,
                               const int* __restrict__ sub, const int* __restrict__ dub,
                               const int* __restrict__ siu, const int* __restrict__ diu) {
    unsigned t = blockIdx.x * blockDim.x + threadIdx.x;
    unsigned gw = t >> 5;
    int lane = threadIdx.x & 31;
    if (gw >= 3u * N_EDGE) return;

    const float* feat;
    float* acc;
    int* cnt;
    int s, d;
    if (gw < N_EDGE) {
        s = suu[gw]; d = duu[gw];
        feat = fu; acc = (float*)g_acc_uu; cnt = g_cnt_uu;
    } else if (gw < 2u * N_EDGE) {
        unsigned e = gw - N_EDGE;
        s = sub[e]; d = dub[e];
        feat = fu; acc = (float*)g_acc_ub; cnt = g_cnt_ub;
    } else {
        unsigned e = gw - 2u * N_EDGE;
        s = siu[e]; d = diu[e];
        feat = fi; acc = (float*)g_acc_iu; cnt = g_cnt_iu;
    }

    float4 v = ((const float4*)(feat + (size_t)s * D))[lane];
    float* p = acc + (size_t)d * D + lane * 4;
    asm volatile("red.global.add.v4.f32 [%0], {%1,%2,%3,%4};"
                 :: "l"(p), "f"(v.x), "f"(v.y), "f"(v.z), "f"(v.w) : "memory");
    if (lane == 0) atomicAdd(cnt + d, 1);
}

// Fused GEMM: out = (acc1/max(c1,1)) @ W1 [+ (acc2/max(c2,1)) @ W2]
//                 + (c1>0)*b1 [+ (c2>0)*b2]
// mode 0: user output (acc_uu/W_uu + acc_iu/W_iu); mode 1: item output (acc_ub/W_ub).
// Tile: BM=64, BN=128 (full), BK=16; 256 threads; 8x4 per-thread register block.
__global__ void gemm_kernel(const float* __restrict__ W1, const float* __restrict__ b1,
                            const float* __restrict__ W2, const float* __restrict__ b2,
                            float* __restrict__ out, int M, int mode) {
    __shared__ __align__(16) float As[16][68];   // [k][m], padded: stride 272B (16B-aligned rows)
    __shared__ __align__(16) float Bs[16][128];  // [k][n]

    const float* A1 = (mode == 0) ? (const float*)g_acc_uu : (const float*)g_acc_ub;
    const int* c1 = (mode == 0) ? g_cnt_uu : g_cnt_ub;
    const float* A2 = (mode == 0) ? (const float*)g_acc_iu : nullptr;
    const int* c2 = g_cnt_iu;
    const bool has2 = (mode == 0);

    const int tid = threadIdx.x;
    const int rg = tid >> 5;          // row group 0..7 (8 rows each)
    const int lane = tid & 31;        // col group (4 cols each)
    const int m0 = blockIdx.x * 64;

    // A-tile loader mapping: one float4 along K per thread
    const int lm = tid >> 2;          // 0..63: row within tile
    const int lk = (tid & 3) * 4;     // 0,4,8,12: k offset
    const int arow = m0 + lm;

    // B-tile loader mapping: 8 floats per thread
    const int wr = tid >> 4;          // 0..15: k row
    const int wc = (tid & 15) * 8;    // 0..120

    float acc[8][4];
#pragma unroll
    for (int i = 0; i < 8; i++)
#pragma unroll
        for (int j = 0; j < 4; j++) acc[i][j] = 0.f;

    const int nsrc = has2 ? 2 : 1;
    for (int sidx = 0; sidx < nsrc; sidx++) {
        const float* A = sidx ? A2 : A1;
        const float* W = sidx ? W2 : W1;
        const int* cc = sidx ? c2 : c1;

        float inv = 1.0f;
        if (arow < M) {
            int c = cc[arow];
            inv = 1.0f / (float)(c > 1 ? c : 1);
        }

        for (int k0 = 0; k0 < D; k0 += 16) {
            float4 av = make_float4(0.f, 0.f, 0.f, 0.f);
            if (arow < M) av = *(const float4*)(A + (size_t)arow * D + k0 + lk);
            As[lk + 0][lm] = av.x * inv;    // fuse mean-normalization here
            As[lk + 1][lm] = av.y * inv;
            As[lk + 2][lm] = av.z * inv;
            As[lk + 3][lm] = av.w * inv;

            float4 w0 = *(const float4*)(W + (size_t)(k0 + wr) * D + wc);
            float4 w1 = *(const float4*)(W + (size_t)(k0 + wr) * D + wc + 4);
            *(float4*)&Bs[wr][wc] = w0;
            *(float4*)&Bs[wr][wc + 4] = w1;
            __syncthreads();

#pragma unroll
            for (int k = 0; k < 16; k++) {
                float4 a0 = *(const float4*)&As[k][rg * 8];       // broadcast (same addr per warp)
                float4 a1 = *(const float4*)&As[k][rg * 8 + 4];
                float4 bb = *(const float4*)&Bs[k][lane * 4];     // conflict-free LDS.128
                float a[8] = {a0.x, a0.y, a0.z, a0.w, a1.x, a1.y, a1.z, a1.w};
#pragma unroll
                for (int i = 0; i < 8; i++) {
                    acc[i][0] += a[i] * bb.x;
                    acc[i][1] += a[i] * bb.y;
                    acc[i][2] += a[i] * bb.z;
                    acc[i][3] += a[i] * bb.w;
                }
            }
            __syncthreads();
        }
    }

    float4 bv1 = *(const float4*)(b1 + lane * 4);
    float4 bv2 = make_float4(0.f, 0.f, 0.f, 0.f);
    if (has2) bv2 = *(const float4*)(b2 + lane * 4);

#pragma unroll
    for (int i = 0; i < 8; i++) {
        int row = m0 + rg * 8 + i;
        if (row >= M) continue;
        float4 o = make_float4(acc[i][0], acc[i][1], acc[i][2], acc[i][3]);
        if (c1[row] > 0) { o.x += bv1.x; o.y += bv1.y; o.z += bv1.z; o.w += bv1.w; }
        if (has2 && c2[row] > 0) { o.x += bv2.x; o.y += bv2.y; o.z += bv2.z; o.w += bv2.w; }
        *(float4*)(out + (size_t)row * D + lane * 4) = o;
    }
}

extern "C" void kernel_launch(void* const* d_in, const int* in_sizes, int n_in,
                              void* d_out, int out_size) {
    const float* feat_user = (const float*)d_in[0];
    const float* feat_item = (const float*)d_in[1];
    const float* W_uu = (const float*)d_in[2];
    const float* b_uu = (const float*)d_in[3];
    const float* W_ub = (const float*)d_in[4];
    const float* b_ub = (const float*)d_in[5];
    const float* W_iu = (const float*)d_in[6];
    const float* b_iu = (const float*)d_in[7];
    const int* src_uu = (const int*)d_in[8];
    const int* dst_uu = (const int*)d_in[9];
    const int* src_ub = (const int*)d_in[10];
    const int* dst_ub = (const int*)d_in[11];
    const int* src_iu = (const int*)d_in[12];
    const int* dst_iu = (const int*)d_in[13];
    float* out = (float*)d_out;  // [out_user (N_USER*D) | out_item (N_ITEM*D)]

    // 1. zero accumulators + counts
    zero_kernel<<<(N_USER * (D / 4) + 255) / 256, 256>>>();

    // 2. edge scatter (all 3 edge types in one grid; warp per edge)
    unsigned total_threads = 3u * N_EDGE * 32u;
    scatter_kernel<<<(total_threads + 255) / 256, 256>>>(
        feat_user, feat_item, src_uu, dst_uu, src_ub, dst_ub, src_iu, dst_iu);

    // 3. fused normalize + GEMM + bias
    int blocks_u = (N_USER + 63) / 64;
    int blocks_i = (N_ITEM + 63) / 64;
    gemm_kernel<<<blocks_u, 256>>>(W_uu, b_uu, W_iu, b_iu, out, N_USER, 0);
    gemm_kernel<<<blocks_i, 256>>>(W_ub, b_ub, nullptr, nullptr,
                                   out + (size_t)N_USER * D, N_ITEM, 1);
}

// round 2
// speedup vs baseline: 1.3607x; 1.3607x over previous
#include <cuda_runtime.h>

#define N_USER 50000
#define N_ITEM 50000
#define N_EDGE 600000
#define D 128
#define NNODE 50000   // per-type node count (user==item==50000)

// ---- scratch (__device__ globals; no allocs allowed) ----
// aggregated (already mean-normalized) features per relation
__device__ float4 g_acc_uu[N_USER * (D / 4)];
__device__ float4 g_acc_ub[N_ITEM * (D / 4)];
__device__ float4 g_acc_iu[N_USER * (D / 4)];
// per-relation in-degree histogram (kept for bias masking)
__device__ int g_cnt[3][NNODE];
// CSR row offsets (exclusive scan of counts) and fill cursors
__device__ int g_off[3][NNODE + 1];
__device__ int g_fill[3][NNODE];
// CSR column (src) arrays
__device__ int g_esrc[3][N_EDGE];

// ---------------------------------------------------------------------------
__global__ void zero_cnt_kernel() {
    int i = blockIdx.x * blockDim.x + threadIdx.x;
    if (i < 3 * NNODE) ((int*)g_cnt)[i] = 0;
}

// histogram of in-degrees, all 3 relations in one grid (thread per edge)
__global__ void hist_kernel(const int* __restrict__ duu,
                            const int* __restrict__ dub,
                            const int* __restrict__ diu) {
    unsigned t = blockIdx.x * blockDim.x + threadIdx.x;
    if (t >= 3u * N_EDGE) return;
    int type = t / N_EDGE;
    unsigned e = t - (unsigned)type * N_EDGE;
    int d = (type == 0) ? duu[e] : (type == 1) ? dub[e] : diu[e];
    atomicAdd(&g_cnt[type][d], 1);
}

// exclusive scan per relation: one block (1024 threads) per relation.
__global__ void scan_kernel() {
    const int type = blockIdx.x;
    const int t = threadIdx.x;
    const int lane = t & 31;
    const int wid = t >> 5;
    __shared__ int warp_sums[32];
    __shared__ int s_carry;
    if (t == 0) { s_carry = 0; g_off[type][0] = 0; }
    __syncthreads();

    for (int base = 0; base < NNODE; base += 1024) {
        int idx = base + t;
        int v = (idx < NNODE) ? g_cnt[type][idx] : 0;
        // warp inclusive scan
        int x = v;
#pragma unroll
        for (int o = 1; o < 32; o <<= 1) {
            int y = __shfl_up_sync(0xffffffffu, x, o);
            if (lane >= o) x += y;
        }
        if (lane == 31) warp_sums[wid] = x;
        __syncthreads();
        if (wid == 0) {
            int w = warp_sums[lane];
            int xs = w;
#pragma unroll
            for (int o = 1; o < 32; o <<= 1) {
                int y = __shfl_up_sync(0xffffffffu, xs, o);
                if (lane >= o) xs += y;
            }
            warp_sums[lane] = xs - w;  // exclusive warp offsets
        }
        __syncthreads();
        int incl = x + warp_sums[wid];           // inclusive scan within chunk
        int carry = s_carry;
        if (idx < NNODE) {
            g_off[type][idx + 1] = carry + incl;
            g_fill[type][idx] = carry + incl - v; // exclusive start = fill cursor
        }
        __syncthreads();
        if (t == 1023) s_carry = carry + incl;
        __syncthreads();
    }
}

// scatter src indices into CSR slots
__global__ void fill_kernel(const int* __restrict__ suu, const int* __restrict__ duu,
                            const int* __restrict__ sub, const int* __restrict__ dub,
                            const int* __restrict__ siu, const int* __restrict__ diu) {
    unsigned t = blockIdx.x * blockDim.x + threadIdx.x;
    if (t >= 3u * N_EDGE) return;
    int type = t / N_EDGE;
    unsigned e = t - (unsigned)type * N_EDGE;
    int s, d;
    if (type == 0)      { s = suu[e]; d = duu[e]; }
    else if (type == 1) { s = sub[e]; d = dub[e]; }
    else                { s = siu[e]; d = diu[e]; }
    int pos = atomicAdd(&g_fill[type][d], 1);
    g_esrc[type][pos] = s;
}

// warp per (relation, dst-node): register-accumulate mean of feat[src]
__global__ void gather_kernel(const float4* __restrict__ fu4,
                              const float4* __restrict__ fi4) {
    unsigned t = blockIdx.x * blockDim.x + threadIdx.x;
    unsigned gw = t >> 5;
    int lane = threadIdx.x & 31;
    if (gw >= 3u * NNODE) return;
    int type = gw / NNODE;
    int node = gw - type * NNODE;

    const float4* feat = (type == 2) ? fi4 : fu4;
    float4* acc = (type == 0) ? g_acc_uu : (type == 1) ? g_acc_ub : g_acc_iu;
    const int* es = g_esrc[type];

    int start = g_off[type][node];
    int end = g_off[type][node + 1];
    int deg = end - start;

    float4 a = make_float4(0.f, 0.f, 0.f, 0.f);
    int e = start;
    for (; e + 4 <= end; e += 4) {
        int s0 = es[e], s1 = es[e + 1], s2 = es[e + 2], s3 = es[e + 3];
        float4 v0 = feat[(size_t)s0 * 32 + lane];
        float4 v1 = feat[(size_t)s1 * 32 + lane];
        float4 v2 = feat[(size_t)s2 * 32 + lane];
        float4 v3 = feat[(size_t)s3 * 32 + lane];
        a.x += v0.x + v1.x + v2.x + v3.x;
        a.y += v0.y + v1.y + v2.y + v3.y;
        a.z += v0.z + v1.z + v2.z + v3.z;
        a.w += v0.w + v1.w + v2.w + v3.w;
    }
    for (; e < end; e++) {
        float4 v = feat[(size_t)es[e] * 32 + lane];
        a.x += v.x; a.y += v.y; a.z += v.z; a.w += v.w;
    }
    float inv = 1.0f / (float)(deg > 1 ? deg : 1);
    a.x *= inv; a.y *= inv; a.z *= inv; a.w *= inv;
    acc[(size_t)node * 32 + lane] = a;
}

// Fused GEMM: out = Anorm1 @ W1 [+ Anorm2 @ W2] + (c1>0)*b1 [+ (c2>0)*b2]
// mode 0: user output (acc_uu/W_uu + acc_iu/W_iu); mode 1: item output (acc_ub/W_ub).
__global__ void gemm_kernel(const float* __restrict__ W1, const float* __restrict__ b1,
                            const float* __restrict__ W2, const float* __restrict__ b2,
                            float* __restrict__ out, int M, int mode) {
    __shared__ __align__(16) float As[16][68];
    __shared__ __align__(16) float Bs[16][128];

    const float* A1 = (mode == 0) ? (const float*)g_acc_uu : (const float*)g_acc_ub;
    const int* c1 = (mode == 0) ? g_cnt[0] : g_cnt[1];
    const float* A2 = (mode == 0) ? (const float*)g_acc_iu : nullptr;
    const int* c2 = g_cnt[2];
    const bool has2 = (mode == 0);

    const int tid = threadIdx.x;
    const int rg = tid >> 5;
    const int lane = tid & 31;
    const int m0 = blockIdx.x * 64;

    const int lm = tid >> 2;
    const int lk = (tid & 3) * 4;
    const int arow = m0 + lm;

    const int wr = tid >> 4;
    const int wc = (tid & 15) * 8;

    float acc[8][4];
#pragma unroll
    for (int i = 0; i < 8; i++)
#pragma unroll
        for (int j = 0; j < 4; j++) acc[i][j] = 0.f;

    const int nsrc = has2 ? 2 : 1;
    for (int sidx = 0; sidx < nsrc; sidx++) {
        const float* A = sidx ? A2 : A1;
        const float* W = sidx ? W2 : W1;

        for (int k0 = 0; k0 < D; k0 += 16) {
            float4 av = make_float4(0.f, 0.f, 0.f, 0.f);
            if (arow < M) av = *(const float4*)(A + (size_t)arow * D + k0 + lk);
            As[lk + 0][lm] = av.x;
            As[lk + 1][lm] = av.y;
            As[lk + 2][lm] = av.z;
            As[lk + 3][lm] = av.w;

            float4 w0 = *(const float4*)(W + (size_t)(k0 + wr) * D + wc);
            float4 w1 = *(const float4*)(W + (size_t)(k0 + wr) * D + wc + 4);
            *(float4*)&Bs[wr][wc] = w0;
            *(float4*)&Bs[wr][wc + 4] = w1;
            __syncthreads();

#pragma unroll
            for (int k = 0; k < 16; k++) {
                float4 a0 = *(const float4*)&As[k][rg * 8];
                float4 a1 = *(const float4*)&As[k][rg * 8 + 4];
                float4 bb = *(const float4*)&Bs[k][lane * 4];
                float a[8] = {a0.x, a0.y, a0.z, a0.w, a1.x, a1.y, a1.z, a1.w};
#pragma unroll
                for (int i = 0; i < 8; i++) {
                    acc[i][0] += a[i] * bb.x;
                    acc[i][1] += a[i] * bb.y;
                    acc[i][2] += a[i] * bb.z;
                    acc[i][3] += a[i] * bb.w;
                }
            }
            __syncthreads();
        }
    }

    float4 bv1 = *(const float4*)(b1 + lane * 4);
    float4 bv2 = make_float4(0.f, 0.f, 0.f, 0.f);
    if (has2) bv2 = *(const float4*)(b2 + lane * 4);

#pragma unroll
    for (int i = 0; i < 8; i++) {
        int row = m0 + rg * 8 + i;
        if (row >= M) continue;
        float4 o = make_float4(acc[i][0], acc[i][1], acc[i][2], acc[i][3]);
        if (c1[row] > 0) { o.x += bv1.x; o.y += bv1.y; o.z += bv1.z; o.w += bv1.w; }
        if (has2 && c2[row] > 0) { o.x += bv2.x; o.y += bv2.y; o.z += bv2.z; o.w += bv2.w; }
        *(float4*)(out + (size_t)row * D + lane * 4) = o;
    }
}

extern "C" void kernel_launch(void* const* d_in, const int* in_sizes, int n_in,
                              void* d_out, int out_size) {
    const float* feat_user = (const float*)d_in[0];
    const float* feat_item = (const float*)d_in[1];
    const float* W_uu = (const float*)d_in[2];
    const float* b_uu = (const float*)d_in[3];
    const float* W_ub = (const float*)d_in[4];
    const float* b_ub = (const float*)d_in[5];
    const float* W_iu = (const float*)d_in[6];
    const float* b_iu = (const float*)d_in[7];
    const int* src_uu = (const int*)d_in[8];
    const int* dst_uu = (const int*)d_in[9];
    const int* src_ub = (const int*)d_in[10];
    const int* dst_ub = (const int*)d_in[11];
    const int* src_iu = (const int*)d_in[12];
    const int* dst_iu = (const int*)d_in[13];
    float* out = (float*)d_out;

    // 1. CSR build
    zero_cnt_kernel<<<(3 * NNODE + 255) / 256, 256>>>();
    hist_kernel<<<(3 * N_EDGE + 255) / 256, 256>>>(dst_uu, dst_ub, dst_iu);
    scan_kernel<<<3, 1024>>>();
    fill_kernel<<<(3 * N_EDGE + 255) / 256, 256>>>(src_uu, dst_uu, src_ub, dst_ub,
                                                   src_iu, dst_iu);
    // 2. gather-side mean aggregation (register accumulation, single store)
    unsigned gthreads = 3u * NNODE * 32u;
    gather_kernel<<<(gthreads + 255) / 256, 256>>>((const float4*)feat_user,
                                                   (const float4*)feat_item);
    // 3. fused GEMM + masked bias
    int blocks_u = (N_USER + 63) / 64;
    int blocks_i = (N_ITEM + 63) / 64;
    gemm_kernel<<<blocks_u, 256>>>(W_uu, b_uu, W_iu, b_iu, out, N_USER, 0);
    gemm_kernel<<<blocks_i, 256>>>(W_ub, b_ub, nullptr, nullptr,
                                   out + (size_t)N_USER * D, N_ITEM, 1);
}

// round 4
// speedup vs baseline: 1.4176x; 1.0418x over previous
#include <cuda_runtime.h>
#include <cuda_fp16.h>

#define N_USER 50000
#define N_ITEM 50000
#define N_EDGE 600000
#define D 128
#define NNODE 50000
#define NE4 (N_EDGE / 4)

// ---- scratch (__device__ globals; no allocs allowed) ----
__device__ float4 g_acc_uu[N_USER * (D / 4)];
__device__ float4 g_acc_ub[N_ITEM * (D / 4)];
__device__ float4 g_acc_iu[N_USER * (D / 4)];
__device__ int g_cnt[3][NNODE];
__device__ int g_off[3][NNODE + 1];
__device__ int g_fill[3][NNODE];
__device__ int g_esrc[3][N_EDGE];
// fp16 feature cache: one row = 128 halves = 256 bytes = 32 uint2  (D/4 uint2!)
__device__ uint2 g_fu_h[N_USER * (D / 4)];
__device__ uint2 g_fi_h[N_ITEM * (D / 4)];

// ---------------------------------------------------------------------------
// fp32 -> fp16 conversion of both feature tables + zero the count arrays.
// One thread per float4 (= per uint2 of output).
__global__ void prep_kernel(const float4* __restrict__ fu, const float4* __restrict__ fi) {
    int i = blockIdx.x * blockDim.x + threadIdx.x;
    const int nv = N_USER * (D / 4);  // 1.6M float4 per tensor
    if (i < nv) {
        float4 v = fu[i];
        __half2 h0 = __floats2half2_rn(v.x, v.y);
        __half2 h1 = __floats2half2_rn(v.z, v.w);
        uint2 o;
        o.x = *(unsigned*)&h0;
        o.y = *(unsigned*)&h1;
        g_fu_h[i] = o;
    } else if (i < 2 * nv) {
        float4 v = fi[i - nv];
        __half2 h0 = __floats2half2_rn(v.x, v.y);
        __half2 h1 = __floats2half2_rn(v.z, v.w);
        uint2 o;
        o.x = *(unsigned*)&h0;
        o.y = *(unsigned*)&h1;
        g_fi_h[i - nv] = o;
    }
    if (i < 3 * NNODE) ((int*)g_cnt)[i] = 0;
}

// in-degree histogram: 4 edges per thread (int4 load, 4 atomics in flight)
__global__ void hist_kernel(const int* __restrict__ duu,
                            const int* __restrict__ dub,
                            const int* __restrict__ diu) {
    unsigned t = blockIdx.x * blockDim.x + threadIdx.x;
    if (t >= 3u * NE4) return;
    int type = t / NE4;
    unsigned e4 = t - (unsigned)type * NE4;
    const int* dst = (type == 0) ? duu : (type == 1) ? dub : diu;
    int4 d = ((const int4*)dst)[e4];
    int* c = g_cnt[type];
    atomicAdd(c + d.x, 1);
    atomicAdd(c + d.y, 1);
    atomicAdd(c + d.z, 1);
    atomicAdd(c + d.w, 1);
}

// exclusive scan per relation: one block (1024 threads) per relation.
__global__ void scan_kernel() {
    const int type = blockIdx.x;
    const int t = threadIdx.x;
    const int lane = t & 31;
    const int wid = t >> 5;
    __shared__ int warp_sums[32];
    __shared__ int s_carry;
    if (t == 0) { s_carry = 0; g_off[type][0] = 0; }
    __syncthreads();

    for (int base = 0; base < NNODE; base += 1024) {
        int idx = base + t;
        int v = (idx < NNODE) ? g_cnt[type][idx] : 0;
        int x = v;
#pragma unroll
        for (int o = 1; o < 32; o <<= 1) {
            int y = __shfl_up_sync(0xffffffffu, x, o);
            if (lane >= o) x += y;
        }
        if (lane == 31) warp_sums[wid] = x;
        __syncthreads();
        if (wid == 0) {
            int w = warp_sums[lane];
            int xs = w;
#pragma unroll
            for (int o = 1; o < 32; o <<= 1) {
                int y = __shfl_up_sync(0xffffffffu, xs, o);
                if (lane >= o) xs += y;
            }
            warp_sums[lane] = xs - w;
        }
        __syncthreads();
        int incl = x + warp_sums[wid];
        int carry = s_carry;
        if (idx < NNODE) {
            g_off[type][idx + 1] = carry + incl;
            g_fill[type][idx] = carry + incl - v;
        }
        __syncthreads();
        if (t == 1023) s_carry = carry + incl;
        __syncthreads();
    }
}

// scatter src indices into CSR slots: 4 edges per thread
__global__ void fill_kernel(const int* __restrict__ suu, const int* __restrict__ duu,
                            const int* __restrict__ sub, const int* __restrict__ dub,
                            const int* __restrict__ siu, const int* __restrict__ diu) {
    unsigned t = blockIdx.x * blockDim.x + threadIdx.x;
    if (t >= 3u * NE4) return;
    int type = t / NE4;
    unsigned e4 = t - (unsigned)type * NE4;
    const int* src = (type == 0) ? suu : (type == 1) ? sub : siu;
    const int* dst = (type == 0) ? duu : (type == 1) ? dub : diu;
    int4 s = ((const int4*)src)[e4];
    int4 d = ((const int4*)dst)[e4];
    int* f = g_fill[type];
    int* es = g_esrc[type];
    int p0 = atomicAdd(f + d.x, 1);
    int p1 = atomicAdd(f + d.y, 1);
    int p2 = atomicAdd(f + d.z, 1);
    int p3 = atomicAdd(f + d.w, 1);
    es[p0] = s.x;
    es[p1] = s.y;
    es[p2] = s.z;
    es[p3] = s.w;
}

// warp per (relation, dst-node): fp16 gather (8B/lane), fp32 register accumulate.
// lane covers halves [lane*4, lane*4+4) of the row.
__global__ void gather_kernel() {
    unsigned t = blockIdx.x * blockDim.x + threadIdx.x;
    unsigned gw = t >> 5;
    int lane = threadIdx.x & 31;
    if (gw >= 3u * NNODE) return;
    int type = gw / NNODE;
    int node = gw - type * NNODE;

    const uint2* feat = (type == 2) ? g_fi_h : g_fu_h;
    float4* acc = (type == 0) ? g_acc_uu : (type == 1) ? g_acc_ub : g_acc_iu;
    const int* es = g_esrc[type];

    int start = g_off[type][node];
    int end = g_off[type][node + 1];
    int deg = end - start;

    float4 a = make_float4(0.f, 0.f, 0.f, 0.f);
    int e = start;
    for (; e + 4 <= end; e += 4) {
        int s0 = es[e], s1 = es[e + 1], s2 = es[e + 2], s3 = es[e + 3];
        uint2 r0 = feat[(size_t)s0 * 32 + lane];
        uint2 r1 = feat[(size_t)s1 * 32 + lane];
        uint2 r2 = feat[(size_t)s2 * 32 + lane];
        uint2 r3 = feat[(size_t)s3 * 32 + lane];
        float2 f;
        f = __half22float2(*(__half2*)&r0.x); a.x += f.x; a.y += f.y;
        f = __half22float2(*(__half2*)&r0.y); a.z += f.x; a.w += f.y;
        f = __half22float2(*(__half2*)&r1.x); a.x += f.x; a.y += f.y;
        f = __half22float2(*(__half2*)&r1.y); a.z += f.x; a.w += f.y;
        f = __half22float2(*(__half2*)&r2.x); a.x += f.x; a.y += f.y;
        f = __half22float2(*(__half2*)&r2.y); a.z += f.x; a.w += f.y;
        f = __half22float2(*(__half2*)&r3.x); a.x += f.x; a.y += f.y;
        f = __half22float2(*(__half2*)&r3.y); a.z += f.x; a.w += f.y;
    }
    for (; e < end; e++) {
        uint2 r = feat[(size_t)es[e] * 32 + lane];
        float2 f;
        f = __half22float2(*(__half2*)&r.x); a.x += f.x; a.y += f.y;
        f = __half22float2(*(__half2*)&r.y); a.z += f.x; a.w += f.y;
    }
    float inv = 1.0f / (float)(deg > 1 ? deg : 1);
    a.x *= inv; a.y *= inv; a.z *= inv; a.w *= inv;
    acc[(size_t)node * 32 + lane] = a;
}

// Merged GEMM, packed f32x2 FMA.
// blocks [0, BU): out_user = acc_uu @ W_uu + acc_iu @ W_iu + masked biases
// blocks [BU, 2BU): out_item = acc_ub @ W_ub + masked bias
__global__ void gemm_kernel(const float* __restrict__ W_uu, const float* __restrict__ b_uu,
                            const float* __restrict__ W_iu, const float* __restrict__ b_iu,
                            const float* __restrict__ W_ub, const float* __restrict__ b_ub,
                            float* __restrict__ out, int BU) {
    __shared__ __align__(16) float As[16][68];   // row stride 272B (16B multiple)
    __shared__ __align__(16) float Bs[16][128];

    int mode, bx;
    if ((int)blockIdx.x < BU) { mode = 0; bx = blockIdx.x; }
    else { mode = 1; bx = blockIdx.x - BU; }

    const float* A1 = (mode == 0) ? (const float*)g_acc_uu : (const float*)g_acc_ub;
    const float* W1 = (mode == 0) ? W_uu : W_ub;
    const float* b1 = (mode == 0) ? b_uu : b_ub;
    const int* c1 = (mode == 0) ? g_cnt[0] : g_cnt[1];
    const float* A2 = (const float*)g_acc_iu;
    const int* c2 = g_cnt[2];
    const bool has2 = (mode == 0);
    float* outp = (mode == 0) ? out : out + (size_t)N_USER * D;
    const int M = NNODE;

    const int tid = threadIdx.x;
    const int rg = tid >> 5;          // 8 row-groups of 8 rows
    const int lane = tid & 31;        // 32 col-groups of 4 cols
    const int m0 = bx * 64;

    const int lm = tid >> 2;
    const int lk = (tid & 3) * 4;
    const int arow = m0 + lm;

    const int wr = tid >> 4;
    const int wc = (tid & 15) * 8;

    // acc2[i2][j]: rows {rg*8+2*i2, rg*8+2*i2+1} packed lo/hi, col lane*4+j
    unsigned long long acc2[4][4];
#pragma unroll
    for (int i = 0; i < 4; i++)
#pragma unroll
        for (int j = 0; j < 4; j++) acc2[i][j] = 0ull;

    const int nsrc = has2 ? 2 : 1;
    for (int sidx = 0; sidx < nsrc; sidx++) {
        const float* A = sidx ? A2 : A1;
        const float* W = sidx ? W_iu : W1;

        for (int k0 = 0; k0 < D; k0 += 16) {
            float4 av = make_float4(0.f, 0.f, 0.f, 0.f);
            if (arow < M) av = *(const float4*)(A + (size_t)arow * D + k0 + lk);
            As[lk + 0][lm] = av.x;
            As[lk + 1][lm] = av.y;
            As[lk + 2][lm] = av.z;
            As[lk + 3][lm] = av.w;

            float4 w0 = *(const float4*)(W + (size_t)(k0 + wr) * D + wc);
            float4 w1 = *(const float4*)(W + (size_t)(k0 + wr) * D + wc + 4);
            *(float4*)&Bs[wr][wc] = w0;
            *(float4*)&Bs[wr][wc + 4] = w1;
            __syncthreads();

#pragma unroll
            for (int k = 0; k < 16; k++) {
                // A pairs: adjacent rows packed in smem -> free 64-bit views (broadcast)
                double2 d0 = *(const double2*)&As[k][rg * 8];
                double2 d1 = *(const double2*)&As[k][rg * 8 + 4];
                unsigned long long ap[4];
                ap[0] = __double_as_longlong(d0.x);
                ap[1] = __double_as_longlong(d0.y);
                ap[2] = __double_as_longlong(d1.x);
                ap[3] = __double_as_longlong(d1.y);
                float4 bb = *(const float4*)&Bs[k][lane * 4];
                unsigned long long bp[4];
                asm("mov.b64 %0, {%1, %1};" : "=l"(bp[0]) : "r"(__float_as_uint(bb.x)));
                asm("mov.b64 %0, {%1, %1};" : "=l"(bp[1]) : "r"(__float_as_uint(bb.y)));
                asm("mov.b64 %0, {%1, %1};" : "=l"(bp[2]) : "r"(__float_as_uint(bb.z)));
                asm("mov.b64 %0, {%1, %1};" : "=l"(bp[3]) : "r"(__float_as_uint(bb.w)));
#pragma unroll
                for (int i = 0; i < 4; i++)
#pragma unroll
                    for (int j = 0; j < 4; j++)
                        asm("fma.rn.f32x2 %0, %1, %2, %0;"
                            : "+l"(acc2[i][j]) : "l"(ap[i]), "l"(bp[j]));
            }
            __syncthreads();
        }
    }

    float4 bv1 = *(const float4*)(b1 + lane * 4);
    float4 bv2 = make_float4(0.f, 0.f, 0.f, 0.f);
    if (has2) bv2 = *(const float4*)(b_iu + lane * 4);

#pragma unroll
    for (int i2 = 0; i2 < 4; i2++) {
        float lo[4], hi[4];
#pragma unroll
        for (int j = 0; j < 4; j++) {
            unsigned rl, rh;
            asm("mov.b64 {%0, %1}, %2;" : "=r"(rl), "=r"(rh) : "l"(acc2[i2][j]));
            lo[j] = __uint_as_float(rl);
            hi[j] = __uint_as_float(rh);
        }
        int row = m0 + rg * 8 + 2 * i2;
#pragma unroll
        for (int h = 0; h < 2; h++) {
            int r = row + h;
            if (r >= M) continue;
            float4 o = h ? make_float4(hi[0], hi[1], hi[2], hi[3])
                         : make_float4(lo[0], lo[1], lo[2], lo[3]);
            if (c1[r] > 0) { o.x += bv1.x; o.y += bv1.y; o.z += bv1.z; o.w += bv1.w; }
            if (has2 && c2[r] > 0) { o.x += bv2.x; o.y += bv2.y; o.z += bv2.z; o.w += bv2.w; }
            *(float4*)(outp + (size_t)r * D + lane * 4) = o;
        }
    }
}

extern "C" void kernel_launch(void* const* d_in, const int* in_sizes, int n_in,
                              void* d_out, int out_size) {
    const float* feat_user = (const float*)d_in[0];
    const float* feat_item = (const float*)d_in[1];
    const float* W_uu = (const float*)d_in[2];
    const float* b_uu = (const float*)d_in[3];
    const float* W_ub = (const float*)d_in[4];
    const float* b_ub = (const float*)d_in[5];
    const float* W_iu = (const float*)d_in[6];
    const float* b_iu = (const float*)d_in[7];
    const int* src_uu = (const int*)d_in[8];
    const int* dst_uu = (const int*)d_in[9];
    const int* src_ub = (const int*)d_in[10];
    const int* dst_ub = (const int*)d_in[11];
    const int* src_iu = (const int*)d_in[12];
    const int* dst_iu = (const int*)d_in[13];
    float* out = (float*)d_out;

    // 1. fp16 conversion + zero counts
    int prep_threads = 2 * N_USER * (D / 4);
    prep_kernel<<<(prep_threads + 255) / 256, 256>>>((const float4*)feat_user,
                                                     (const float4*)feat_item);
    // 2. CSR build
    hist_kernel<<<(3 * NE4 + 255) / 256, 256>>>(dst_uu, dst_ub, dst_iu);
    scan_kernel<<<3, 1024>>>();
    fill_kernel<<<(3 * NE4 + 255) / 256, 256>>>(src_uu, dst_uu, src_ub, dst_ub,
                                                src_iu, dst_iu);
    // 3. gather-side mean aggregation (fp16 reads, fp32 accumulate)
    unsigned gthreads = 3u * NNODE * 32u;
    gather_kernel<<<(gthreads + 255) / 256, 256>>>();
    // 4. merged GEMM (f32x2) + masked bias
    int BU = (N_USER + 63) / 64;
    int BI = (N_ITEM + 63) / 64;
    gemm_kernel<<<BU + BI, 256>>>(W_uu, b_uu, W_iu, b_iu, W_ub, b_ub, out, BU);
}

// round 6
// speedup vs baseline: 1.9529x; 1.3777x over previous
#include <cuda_runtime.h>
#include <cuda_fp16.h>

#define N_USER 50000
#define N_ITEM 50000
#define N_EDGE 600000
#define D 128
#define NNODE 50000
#define NE4 (N_EDGE / 4)

// ---- scratch (__device__ globals) ----
__device__ int g_cnt[3][NNODE];        // zeroed by scan after use (invariant: 0 at launch entry)
__device__ int g_off[3][NNODE + 1];
__device__ int g_fill[3][NNODE];
__device__ int g_esrc[3][N_EDGE];
// fp16 feature cache: row = 128 halves = 32 uint2
__device__ uint2 g_fu_h[N_USER * (D / 4)];
__device__ uint2 g_fi_h[N_ITEM * (D / 4)];
// fp16 aggregated means: [0]=uu, [1]=ub, [2]=iu ; row = 32 uint2
__device__ uint2 g_agg[3][NNODE * (D / 4)];
// fp16 TRANSPOSED weights: Wt[n*128 + k] = W[k*128 + n]; [0]=W_uu, [1]=W_iu, [2]=W_ub
__device__ __half g_Wt[3][D * D];

// ---------------------------------------------------------------------------
// prep: fp32->fp16 features, fp16 transposed weights, 4-wide in-degree hist.
// g_cnt arrives zeroed (module init or previous scan).
__global__ void prep_kernel(const float4* __restrict__ fu, const float4* __restrict__ fi,
                            const float* __restrict__ Wuu, const float* __restrict__ Wiu,
                            const float* __restrict__ Wub,
                            const int* __restrict__ duu, const int* __restrict__ dub,
                            const int* __restrict__ diu) {
    int i = blockIdx.x * blockDim.x + threadIdx.x;
    const int nv = N_USER * (D / 4);  // 1.6M float4 per feature tensor
    if (i < nv) {
        float4 v = fu[i];
        __half2 h0 = __floats2half2_rn(v.x, v.y);
        __half2 h1 = __floats2half2_rn(v.z, v.w);
        uint2 o; o.x = *(unsigned*)&h0; o.y = *(unsigned*)&h1;
        g_fu_h[i] = o;
    } else if (i < 2 * nv) {
        float4 v = fi[i - nv];
        __half2 h0 = __floats2half2_rn(v.x, v.y);
        __half2 h1 = __floats2half2_rn(v.z, v.w);
        uint2 o; o.x = *(unsigned*)&h0; o.y = *(unsigned*)&h1;
        g_fi_h[i - nv] = o;
    }
    if (i < 3 * D * D) {  // 49152 transposed weight elements
        int m = i >> 14;
        int r = i & (D * D - 1);
        int n = r >> 7;
        int k = r & 127;
        const float* W = (m == 0) ? Wuu : (m == 1) ? Wiu : Wub;
        g_Wt[m][(n << 7) + k] = __float2half(W[(k << 7) + n]);
    }
    if (i < 3 * NE4) {  // histogram, 4 edges/thread
        int type = i / NE4;
        unsigned e4 = i - (unsigned)type * NE4;
        const int* dst = (type == 0) ? duu : (type == 1) ? dub : diu;
        int4 d = ((const int4*)dst)[e4];
        int* c = g_cnt[type];
        atomicAdd(c + d.x, 1);
        atomicAdd(c + d.y, 1);
        atomicAdd(c + d.z, 1);
        atomicAdd(c + d.w, 1);
    }
}

// exclusive scan per relation; also re-zeroes g_cnt for the next invocation.
__global__ void scan_kernel() {
    const int type = blockIdx.x;
    const int t = threadIdx.x;
    const int lane = t & 31;
    const int wid = t >> 5;
    __shared__ int warp_sums[32];
    __shared__ int s_carry;
    if (t == 0) { s_carry = 0; g_off[type][0] = 0; }
    __syncthreads();

    for (int base = 0; base < NNODE; base += 1024) {
        int idx = base + t;
        int v = 0;
        if (idx < NNODE) {
            v = g_cnt[type][idx];
            g_cnt[type][idx] = 0;  // restore invariant for next launch
        }
        int x = v;
#pragma unroll
        for (int o = 1; o < 32; o <<= 1) {
            int y = __shfl_up_sync(0xffffffffu, x, o);
            if (lane >= o) x += y;
        }
        if (lane == 31) warp_sums[wid] = x;
        __syncthreads();
        if (wid == 0) {
            int w = warp_sums[lane];
            int xs = w;
#pragma unroll
            for (int o = 1; o < 32; o <<= 1) {
                int y = __shfl_up_sync(0xffffffffu, xs, o);
                if (lane >= o) xs += y;
            }
            warp_sums[lane] = xs - w;
        }
        __syncthreads();
        int incl = x + warp_sums[wid];
        int carry = s_carry;
        if (idx < NNODE) {
            g_off[type][idx + 1] = carry + incl;
            g_fill[type][idx] = carry + incl - v;
        }
        __syncthreads();
        if (t == 1023) s_carry = carry + incl;
        __syncthreads();
    }
}

// scatter src indices into CSR slots: 4 edges per thread
__global__ void fill_kernel(const int* __restrict__ suu, const int* __restrict__ duu,
                            const int* __restrict__ sub, const int* __restrict__ dub,
                            const int* __restrict__ siu, const int* __restrict__ diu) {
    unsigned t = blockIdx.x * blockDim.x + threadIdx.x;
    if (t >= 3u * NE4) return;
    int type = t / NE4;
    unsigned e4 = t - (unsigned)type * NE4;
    const int* src = (type == 0) ? suu : (type == 1) ? sub : siu;
    const int* dst = (type == 0) ? duu : (type == 1) ? dub : diu;
    int4 s = ((const int4*)src)[e4];
    int4 d = ((const int4*)dst)[e4];
    int* f = g_fill[type];
    int* es = g_esrc[type];
    int p0 = atomicAdd(f + d.x, 1);
    int p1 = atomicAdd(f + d.y, 1);
    int p2 = atomicAdd(f + d.z, 1);
    int p3 = atomicAdd(f + d.w, 1);
    es[p0] = s.x;
    es[p1] = s.y;
    es[p2] = s.z;
    es[p3] = s.w;
}

// warp per (relation, dst-node): fp16 gather, fp32 accumulate, fp16 mean out.
__global__ void gather_kernel() {
    unsigned t = blockIdx.x * blockDim.x + threadIdx.x;
    unsigned gw = t >> 5;
    int lane = threadIdx.x & 31;
    if (gw >= 3u * NNODE) return;
    int type = gw / NNODE;
    int node = gw - type * NNODE;

    const uint2* feat = (type == 2) ? g_fi_h : g_fu_h;
    const int* es = g_esrc[type];

    int start = g_off[type][node];
    int end = g_off[type][node + 1];
    int deg = end - start;

    float4 a = make_float4(0.f, 0.f, 0.f, 0.f);
    int e = start;
    for (; e + 8 <= end; e += 8) {
        uint2 r[8];
#pragma unroll
        for (int u = 0; u < 8; u++) r[u] = feat[(size_t)es[e + u] * 32 + lane];
#pragma unroll
        for (int u = 0; u < 8; u++) {
            float2 f;
            f = __half22float2(*(__half2*)&r[u].x); a.x += f.x; a.y += f.y;
            f = __half22float2(*(__half2*)&r[u].y); a.z += f.x; a.w += f.y;
        }
    }
    for (; e < end; e++) {
        uint2 r = feat[(size_t)es[e] * 32 + lane];
        float2 f;
        f = __half22float2(*(__half2*)&r.x); a.x += f.x; a.y += f.y;
        f = __half22float2(*(__half2*)&r.y); a.z += f.x; a.w += f.y;
    }
    float inv = 1.0f / (float)(deg > 1 ? deg : 1);
    __half2 h0 = __floats2half2_rn(a.x * inv, a.y * inv);
    __half2 h1 = __floats2half2_rn(a.z * inv, a.w * inv);
    uint2 o; o.x = *(unsigned*)&h0; o.y = *(unsigned*)&h1;
    g_agg[type][(size_t)node * 32 + lane] = o;
}

// ---------------------------------------------------------------------------
// HMMA GEMM. BM=64, BN=128(full D), K=128 fully smem-resident.
// 256 threads = 8 warps, warp tile 32x32 (warpRow = wid&1, warpCol = wid>>1).
// smem rows are 256B with XOR swizzle: 16B-group index c16 -> c16 ^ (row&7).
// blocks [0,BU): out_user = agg_uu@W_uu + agg_iu@W_iu + masked biases
// blocks [BU,2BU): out_item = agg_ub@W_ub + masked bias
__global__ void gemm_hmma_kernel(const float* __restrict__ b_uu,
                                 const float* __restrict__ b_iu,
                                 const float* __restrict__ b_ub,
                                 float* __restrict__ out, int BU) {
    __shared__ __align__(16) __half sA[64 * 128];   // 16KB
    __shared__ __align__(16) __half sB[128 * 128];  // 32KB  (total 48KB)

    int mode, bx;
    if ((int)blockIdx.x < BU) { mode = 0; bx = blockIdx.x; }
    else { mode = 1; bx = blockIdx.x - BU; }
    const int m0 = bx * 64;

    const int tid = threadIdx.x;
    const int wid = tid >> 5;
    const int lane = tid & 31;
    const int g = lane >> 2;       // 0..7
    const int tq = lane & 3;       // 0..3
    const int wr = (wid & 1) * 32;   // warp row base (0/32)
    const int wc = (wid >> 1) * 32;  // warp col base (0/32/64/96)

    float dacc[2][4][4];
#pragma unroll
    for (int mt = 0; mt < 2; mt++)
#pragma unroll
        for (int nt = 0; nt < 4; nt++)
#pragma unroll
            for (int q = 0; q < 4; q++) dacc[mt][nt][q] = 0.f;

    const int nsrc = (mode == 0) ? 2 : 1;
    for (int s = 0; s < nsrc; s++) {
        const uint2* A = (mode == 0) ? (s ? g_agg[2] : g_agg[0]) : g_agg[1];
        const __half* Wt = (mode == 0) ? (s ? g_Wt[1] : g_Wt[0]) : g_Wt[2];

        if (s) __syncthreads();  // protect smem reuse across sources
        // load A tile: 64 rows x 16 uint4 per row
#pragma unroll
        for (int it = 0; it < 4; it++) {
            int idx = it * 256 + tid;           // 0..1023
            int r = idx >> 4;                   // 0..63
            int c16 = idx & 15;
            int grow = m0 + r;
            uint4 v = make_uint4(0u, 0u, 0u, 0u);
            if (grow < NNODE) v = ((const uint4*)(A + (size_t)grow * 32))[c16];
            *(uint4*)((char*)sA + r * 256 + ((c16 ^ (r & 7)) * 16)) = v;
        }
        // load B (transposed W): 128 rows(n) x 16 uint4
#pragma unroll
        for (int it = 0; it < 8; it++) {
            int idx = it * 256 + tid;           // 0..2047
            int r = idx >> 4;
            int c16 = idx & 15;
            uint4 v = ((const uint4*)Wt)[idx];
            *(uint4*)((char*)sB + r * 256 + ((c16 ^ (r & 7)) * 16)) = v;
        }
        __syncthreads();

#pragma unroll
        for (int ks = 0; ks < 8; ks++) {
            const int k0 = ks * 16;
            // swizzled 4B word fetch: row*256 + ((w ^ ((row&7)<<2)) << 2), w = half_idx/2
            unsigned a[2][4];
#pragma unroll
            for (int mt = 0; mt < 2; mt++) {
                int r0 = wr + mt * 16 + g;
                int r1 = r0 + 8;
                int w0 = (k0 >> 1) + tq;        // k0 + 2t
                int w1 = w0 + 4;                // k0 + 2t + 8
                a[mt][0] = *(unsigned*)((char*)sA + r0 * 256 + ((w0 ^ ((r0 & 7) << 2)) << 2));
                a[mt][1] = *(unsigned*)((char*)sA + r1 * 256 + ((w0 ^ ((r1 & 7) << 2)) << 2));
                a[mt][2] = *(unsigned*)((char*)sA + r0 * 256 + ((w1 ^ ((r0 & 7) << 2)) << 2));
                a[mt][3] = *(unsigned*)((char*)sA + r1 * 256 + ((w1 ^ ((r1 & 7) << 2)) << 2));
            }
#pragma unroll
            for (int nt = 0; nt < 4; nt++) {
                int n = wc + nt * 8 + g;
                int w0 = (k0 >> 1) + tq;
                int w1 = w0 + 4;
                unsigned b0 = *(unsigned*)((char*)sB + n * 256 + ((w0 ^ ((n & 7) << 2)) << 2));
                unsigned b1 = *(unsigned*)((char*)sB + n * 256 + ((w1 ^ ((n & 7) << 2)) << 2));
#pragma unroll
                for (int mt = 0; mt < 2; mt++) {
                    asm volatile(
                        "mma.sync.aligned.m16n8k16.row.col.f32.f16.f16.f32 "
                        "{%0,%1,%2,%3}, {%4,%5,%6,%7}, {%8,%9}, {%0,%1,%2,%3};"
                        : "+f"(dacc[mt][nt][0]), "+f"(dacc[mt][nt][1]),
                          "+f"(dacc[mt][nt][2]), "+f"(dacc[mt][nt][3])
                        : "r"(a[mt][0]), "r"(a[mt][1]), "r"(a[mt][2]), "r"(a[mt][3]),
                          "r"(b0), "r"(b1));
                }
            }
        }
    }

    // epilogue: masked bias + store
    float* outp = (mode == 0) ? out : out + (size_t)N_USER * D;
    const float* bias1 = (mode == 0) ? b_uu : b_ub;
    const int* off1 = (mode == 0) ? g_off[0] : g_off[1];
    const int* off2 = g_off[2];

    float2 bv1[4], bv2[4];
#pragma unroll
    for (int nt = 0; nt < 4; nt++) {
        int col = wc + nt * 8 + tq * 2;
        bv1[nt] = *(const float2*)(bias1 + col);
        bv2[nt] = (mode == 0) ? *(const float2*)(b_iu + col) : make_float2(0.f, 0.f);
    }

#pragma unroll
    for (int mt = 0; mt < 2; mt++) {
#pragma unroll
        for (int half_m = 0; half_m < 2; half_m++) {
            int row = m0 + wr + mt * 16 + half_m * 8 + g;
            if (row >= NNODE) continue;
            bool m1 = off1[row + 1] > off1[row];
            bool m2 = (mode == 0) && (off2[row + 1] > off2[row]);
#pragma unroll
            for (int nt = 0; nt < 4; nt++) {
                int col = wc + nt * 8 + tq * 2;
                float2 v;
                v.x = dacc[mt][nt][half_m * 2 + 0];
                v.y = dacc[mt][nt][half_m * 2 + 1];
                if (m1) { v.x += bv1[nt].x; v.y += bv1[nt].y; }
                if (m2) { v.x += bv2[nt].x; v.y += bv2[nt].y; }
                *(float2*)(outp + (size_t)row * D + col) = v;
            }
        }
    }
}

extern "C" void kernel_launch(void* const* d_in, const int* in_sizes, int n_in,
                              void* d_out, int out_size) {
    const float* feat_user = (const float*)d_in[0];
    const float* feat_item = (const float*)d_in[1];
    const float* W_uu = (const float*)d_in[2];
    const float* b_uu = (const float*)d_in[3];
    const float* W_ub = (const float*)d_in[4];
    const float* b_ub = (const float*)d_in[5];
    const float* W_iu = (const float*)d_in[6];
    const float* b_iu = (const float*)d_in[7];
    const int* src_uu = (const int*)d_in[8];
    const int* dst_uu = (const int*)d_in[9];
    const int* src_ub = (const int*)d_in[10];
    const int* dst_ub = (const int*)d_in[11];
    const int* src_iu = (const int*)d_in[12];
    const int* dst_iu = (const int*)d_in[13];
    float* out = (float*)d_out;

    // 1. fp16 features + transposed fp16 weights + in-degree histogram
    int prep_threads = 2 * N_USER * (D / 4);
    prep_kernel<<<(prep_threads + 255) / 256, 256>>>(
        (const float4*)feat_user, (const float4*)feat_item,
        W_uu, W_iu, W_ub, dst_uu, dst_ub, dst_iu);
    // 2. scan (also re-zeroes counts for next launch)
    scan_kernel<<<3, 1024>>>();
    // 3. CSR fill
    fill_kernel<<<(3 * NE4 + 255) / 256, 256>>>(src_uu, dst_uu, src_ub, dst_ub,
                                                src_iu, dst_iu);
    // 4. gather-side mean aggregation (fp16 in/out, fp32 accumulate)
    unsigned gthreads = 3u * NNODE * 32u;
    gather_kernel<<<(gthreads + 255) / 256, 256>>>();
    // 5. tensor-core GEMM + masked bias
    int BU = (N_USER + 63) / 64;
    int BI = (N_ITEM + 63) / 64;
    gemm_hmma_kernel<<<BU + BI, 256>>>(b_uu, b_iu, b_ub, out, BU);
}

// round 8
// speedup vs baseline: 1.9573x; 1.0022x over previous
#include <cuda_runtime.h>
#include <cuda_fp16.h>

#define N_USER 50000
#define N_ITEM 50000
#define N_EDGE 600000
#define D 128
#define NNODE 50000
#define NE4 (N_EDGE / 4)

// ---- scratch (__device__ globals) ----
__device__ int g_cnt[3][NNODE];        // zeroed by scan after use (invariant: 0 at entry)
__device__ int g_off[3][NNODE + 1];
__device__ int g_fill[3][NNODE];
__device__ int g_esrc[3][N_EDGE];
// fp16 feature cache: row = 128 halves = 32 uint2
__device__ uint2 g_fu_h[N_USER * (D / 4)];
__device__ uint2 g_fi_h[N_ITEM * (D / 4)];
// fp16 aggregated means: [0]=uu, [1]=ub, [2]=iu
__device__ uint2 g_agg[3][NNODE * (D / 4)];
// fp16 TRANSPOSED weights: Wt[n*128 + k] = W[k*128 + n]; [0]=W_uu, [1]=W_iu, [2]=W_ub
__device__ __half g_Wt[3][D * D];

// ---------------------------------------------------------------------------
// prep: fp32->fp16 features, fp16 transposed weights, 4-wide in-degree hist.
// (R6-proven structure: hist merged here, single stream.)
__global__ void prep_kernel(const float4* __restrict__ fu, const float4* __restrict__ fi,
                            const float* __restrict__ Wuu, const float* __restrict__ Wiu,
                            const float* __restrict__ Wub,
                            const int* __restrict__ duu, const int* __restrict__ dub,
                            const int* __restrict__ diu) {
    int i = blockIdx.x * blockDim.x + threadIdx.x;
    const int nv = N_USER * (D / 4);
    if (i < nv) {
        float4 v = fu[i];
        __half2 h0 = __floats2half2_rn(v.x, v.y);
        __half2 h1 = __floats2half2_rn(v.z, v.w);
        uint2 o; o.x = *(unsigned*)&h0; o.y = *(unsigned*)&h1;
        g_fu_h[i] = o;
    } else if (i < 2 * nv) {
        float4 v = fi[i - nv];
        __half2 h0 = __floats2half2_rn(v.x, v.y);
        __half2 h1 = __floats2half2_rn(v.z, v.w);
        uint2 o; o.x = *(unsigned*)&h0; o.y = *(unsigned*)&h1;
        g_fi_h[i - nv] = o;
    }
    if (i < 3 * D * D) {
        int m = i >> 14;
        int r = i & (D * D - 1);
        int n = r >> 7;
        int k = r & 127;
        const float* W = (m == 0) ? Wuu : (m == 1) ? Wiu : Wub;
        g_Wt[m][(n << 7) + k] = __float2half(W[(k << 7) + n]);
    }
    if (i < 3 * NE4) {
        int type = i / NE4;
        unsigned e4 = i - (unsigned)type * NE4;
        const int* dst = (type == 0) ? duu : (type == 1) ? dub : diu;
        int4 d = ((const int4*)dst)[e4];
        int* c = g_cnt[type];
        atomicAdd(c + d.x, 1);
        atomicAdd(c + d.y, 1);
        atomicAdd(c + d.z, 1);
        atomicAdd(c + d.w, 1);
    }
}

// exclusive scan per relation; re-zeroes g_cnt for the next invocation.
__global__ void scan_kernel() {
    const int type = blockIdx.x;
    const int t = threadIdx.x;
    const int lane = t & 31;
    const int wid = t >> 5;
    __shared__ int warp_sums[32];
    __shared__ int s_carry;
    if (t == 0) { s_carry = 0; g_off[type][0] = 0; }
    __syncthreads();

    for (int base = 0; base < NNODE; base += 1024) {
        int idx = base + t;
        int v = 0;
        if (idx < NNODE) {
            v = g_cnt[type][idx];
            g_cnt[type][idx] = 0;
        }
        int x = v;
#pragma unroll
        for (int o = 1; o < 32; o <<= 1) {
            int y = __shfl_up_sync(0xffffffffu, x, o);
            if (lane >= o) x += y;
        }
        if (lane == 31) warp_sums[wid] = x;
        __syncthreads();
        if (wid == 0) {
            int w = warp_sums[lane];
            int xs = w;
#pragma unroll
            for (int o = 1; o < 32; o <<= 1) {
                int y = __shfl_up_sync(0xffffffffu, xs, o);
                if (lane >= o) xs += y;
            }
            warp_sums[lane] = xs - w;
        }
        __syncthreads();
        int incl = x + warp_sums[wid];
        int carry = s_carry;
        if (idx < NNODE) {
            g_off[type][idx + 1] = carry + incl;
            g_fill[type][idx] = carry + incl - v;
        }
        __syncthreads();
        if (t == 1023) s_carry = carry + incl;
        __syncthreads();
    }
}

// scatter src indices into CSR slots: 4 edges per thread
__global__ void fill_kernel(const int* __restrict__ suu, const int* __restrict__ duu,
                            const int* __restrict__ sub, const int* __restrict__ dub,
                            const int* __restrict__ siu, const int* __restrict__ diu) {
    unsigned t = blockIdx.x * blockDim.x + threadIdx.x;
    if (t >= 3u * NE4) return;
    int type = t / NE4;
    unsigned e4 = t - (unsigned)type * NE4;
    const int* src = (type == 0) ? suu : (type == 1) ? sub : siu;
    const int* dst = (type == 0) ? duu : (type == 1) ? dub : diu;
    int4 s = ((const int4*)src)[e4];
    int4 d = ((const int4*)dst)[e4];
    int* f = g_fill[type];
    int* es = g_esrc[type];
    int p0 = atomicAdd(f + d.x, 1);
    int p1 = atomicAdd(f + d.y, 1);
    int p2 = atomicAdd(f + d.z, 1);
    int p3 = atomicAdd(f + d.w, 1);
    es[p0] = s.x;
    es[p1] = s.y;
    es[p2] = s.z;
    es[p3] = s.w;
}

// warp per (relation, dst-node): fp16 gather, fp32 accumulate, fp16 mean out.
// 32-bit index math; predicated 4-wide loads with zero fill (no serial tail).
__global__ void gather_kernel() {
    unsigned t = blockIdx.x * blockDim.x + threadIdx.x;
    unsigned gw = t >> 5;
    int lane = threadIdx.x & 31;
    if (gw >= 3u * NNODE) return;
    int type = gw / NNODE;
    int node = gw - type * NNODE;

    const uint2* fl = ((type == 2) ? g_fi_h : g_fu_h) + lane;  // lane base pointer
    const int* es = g_esrc[type];

    int start = g_off[type][node];
    int end = g_off[type][node + 1];
    int deg = end - start;

    float4 a = make_float4(0.f, 0.f, 0.f, 0.f);
    for (int e = start; e < end; e += 4) {
        int n = end - e;
        uint2 r[4];
#pragma unroll
        for (int u = 0; u < 4; u++) {
            r[u].x = 0u; r[u].y = 0u;
            if (u < n) r[u] = fl[(unsigned)es[e + u] << 5];
        }
#pragma unroll
        for (int u = 0; u < 4; u++) {
            float2 f;
            f = __half22float2(*(__half2*)&r[u].x); a.x += f.x; a.y += f.y;
            f = __half22float2(*(__half2*)&r[u].y); a.z += f.x; a.w += f.y;
        }
    }
    float inv = 1.0f / (float)(deg > 1 ? deg : 1);
    __half2 h0 = __floats2half2_rn(a.x * inv, a.y * inv);
    __half2 h1 = __floats2half2_rn(a.z * inv, a.w * inv);
    uint2 o; o.x = *(unsigned*)&h0; o.y = *(unsigned*)&h1;
    g_agg[type][(unsigned)node * 32u + (unsigned)lane] = o;
}

// ---------------------------------------------------------------------------
// HMMA GEMM (unchanged from R6 — verified correct).
__global__ void gemm_hmma_kernel(const float* __restrict__ b_uu,
                                 const float* __restrict__ b_iu,
                                 const float* __restrict__ b_ub,
                                 float* __restrict__ out, int BU) {
    __shared__ __align__(16) __half sA[64 * 128];
    __shared__ __align__(16) __half sB[128 * 128];

    int mode, bx;
    if ((int)blockIdx.x < BU) { mode = 0; bx = blockIdx.x; }
    else { mode = 1; bx = blockIdx.x - BU; }
    const int m0 = bx * 64;

    const int tid = threadIdx.x;
    const int wid = tid >> 5;
    const int lane = tid & 31;
    const int g = lane >> 2;
    const int tq = lane & 3;
    const int wr = (wid & 1) * 32;
    const int wc = (wid >> 1) * 32;

    float dacc[2][4][4];
#pragma unroll
    for (int mt = 0; mt < 2; mt++)
#pragma unroll
        for (int nt = 0; nt < 4; nt++)
#pragma unroll
            for (int q = 0; q < 4; q++) dacc[mt][nt][q] = 0.f;

    const int nsrc = (mode == 0) ? 2 : 1;
    for (int s = 0; s < nsrc; s++) {
        const uint2* A = (mode == 0) ? (s ? g_agg[2] : g_agg[0]) : g_agg[1];
        const __half* Wt = (mode == 0) ? (s ? g_Wt[1] : g_Wt[0]) : g_Wt[2];

        if (s) __syncthreads();
#pragma unroll
        for (int it = 0; it < 4; it++) {
            int idx = it * 256 + tid;
            int r = idx >> 4;
            int c16 = idx & 15;
            int grow = m0 + r;
            uint4 v = make_uint4(0u, 0u, 0u, 0u);
            if (grow < NNODE) v = ((const uint4*)(A + (size_t)grow * 32))[c16];
            *(uint4*)((char*)sA + r * 256 + ((c16 ^ (r & 7)) * 16)) = v;
        }
#pragma unroll
        for (int it = 0; it < 8; it++) {
            int idx = it * 256 + tid;
            int r = idx >> 4;
            int c16 = idx & 15;
            uint4 v = ((const uint4*)Wt)[idx];
            *(uint4*)((char*)sB + r * 256 + ((c16 ^ (r & 7)) * 16)) = v;
        }
        __syncthreads();

#pragma unroll
        for (int ks = 0; ks < 8; ks++) {
            const int k0 = ks * 16;
            unsigned a[2][4];
#pragma unroll
            for (int mt = 0; mt < 2; mt++) {
                int r0 = wr + mt * 16 + g;
                int r1 = r0 + 8;
                int w0 = (k0 >> 1) + tq;
                int w1 = w0 + 4;
                a[mt][0] = *(unsigned*)((char*)sA + r0 * 256 + ((w0 ^ ((r0 & 7) << 2)) << 2));
                a[mt][1] = *(unsigned*)((char*)sA + r1 * 256 + ((w0 ^ ((r1 & 7) << 2)) << 2));
                a[mt][2] = *(unsigned*)((char*)sA + r0 * 256 + ((w1 ^ ((r0 & 7) << 2)) << 2));
                a[mt][3] = *(unsigned*)((char*)sA + r1 * 256 + ((w1 ^ ((r1 & 7) << 2)) << 2));
            }
#pragma unroll
            for (int nt = 0; nt < 4; nt++) {
                int n = wc + nt * 8 + g;
                int w0 = (k0 >> 1) + tq;
                int w1 = w0 + 4;
                unsigned b0 = *(unsigned*)((char*)sB + n * 256 + ((w0 ^ ((n & 7) << 2)) << 2));
                unsigned b1 = *(unsigned*)((char*)sB + n * 256 + ((w1 ^ ((n & 7) << 2)) << 2));
#pragma unroll
                for (int mt = 0; mt < 2; mt++) {
                    asm volatile(
                        "mma.sync.aligned.m16n8k16.row.col.f32.f16.f16.f32 "
                        "{%0,%1,%2,%3}, {%4,%5,%6,%7}, {%8,%9}, {%0,%1,%2,%3};"
                        : "+f"(dacc[mt][nt][0]), "+f"(dacc[mt][nt][1]),
                          "+f"(dacc[mt][nt][2]), "+f"(dacc[mt][nt][3])
                        : "r"(a[mt][0]), "r"(a[mt][1]), "r"(a[mt][2]), "r"(a[mt][3]),
                          "r"(b0), "r"(b1));
                }
            }
        }
    }

    float* outp = (mode == 0) ? out : out + (size_t)N_USER * D;
    const float* bias1 = (mode == 0) ? b_uu : b_ub;
    const int* off1 = (mode == 0) ? g_off[0] : g_off[1];
    const int* off2 = g_off[2];

    float2 bv1[4], bv2[4];
#pragma unroll
    for (int nt = 0; nt < 4; nt++) {
        int col = wc + nt * 8 + tq * 2;
        bv1[nt] = *(const float2*)(bias1 + col);
        bv2[nt] = (mode == 0) ? *(const float2*)(b_iu + col) : make_float2(0.f, 0.f);
    }

#pragma unroll
    for (int mt = 0; mt < 2; mt++) {
#pragma unroll
        for (int half_m = 0; half_m < 2; half_m++) {
            int row = m0 + wr + mt * 16 + half_m * 8 + g;
            if (row >= NNODE) continue;
            bool m1 = off1[row + 1] > off1[row];
            bool m2 = (mode == 0) && (off2[row + 1] > off2[row]);
#pragma unroll
            for (int nt = 0; nt < 4; nt++) {
                int col = wc + nt * 8 + tq * 2;
                float2 v;
                v.x = dacc[mt][nt][half_m * 2 + 0];
                v.y = dacc[mt][nt][half_m * 2 + 1];
                if (m1) { v.x += bv1[nt].x; v.y += bv1[nt].y; }
                if (m2) { v.x += bv2[nt].x; v.y += bv2[nt].y; }
                *(float2*)(outp + (size_t)row * D + col) = v;
            }
        }
    }
}

extern "C" void kernel_launch(void* const* d_in, const int* in_sizes, int n_in,
                              void* d_out, int out_size) {
    const float* feat_user = (const float*)d_in[0];
    const float* feat_item = (const float*)d_in[1];
    const float* W_uu = (const float*)d_in[2];
    const float* b_uu = (const float*)d_in[3];
    const float* W_ub = (const float*)d_in[4];
    const float* b_ub = (const float*)d_in[5];
    const float* W_iu = (const float*)d_in[6];
    const float* b_iu = (const float*)d_in[7];
    const int* src_uu = (const int*)d_in[8];
    const int* dst_uu = (const int*)d_in[9];
    const int* src_ub = (const int*)d_in[10];
    const int* dst_ub = (const int*)d_in[11];
    const int* src_iu = (const int*)d_in[12];
    const int* dst_iu = (const int*)d_in[13];
    float* out = (float*)d_out;

    // 1. fp16 features + transposed fp16 weights + in-degree histogram
    int prep_threads = 2 * N_USER * (D / 4);
    prep_kernel<<<(prep_threads + 255) / 256, 256>>>(
        (const float4*)feat_user, (const float4*)feat_item,
        W_uu, W_iu, W_ub, dst_uu, dst_ub, dst_iu);
    // 2. scan (also re-zeroes counts for next launch)
    scan_kernel<<<3, 1024>>>();
    // 3. CSR fill
    fill_kernel<<<(3 * NE4 + 255) / 256, 256>>>(src_uu, dst_uu, src_ub, dst_ub,
                                                src_iu, dst_iu);
    // 4. gather-side mean aggregation (fp16 in/out, fp32 accumulate)
    unsigned gthreads = 3u * NNODE * 32u;
    gather_kernel<<<(gthreads + 255) / 256, 256>>>();
    // 5. tensor-core GEMM + masked bias
    int BU = (N_USER + 63) / 64;
    int BI = (N_ITEM + 63) / 64;
    gemm_hmma_kernel<<<BU + BI, 256>>>(b_uu, b_iu, b_ub, out, BU);
}

// round 9
// speedup vs baseline: 2.0791x; 1.0623x over previous
#include <cuda_runtime.h>
#include <cuda_fp16.h>

#define N_USER 50000
#define N_ITEM 50000
#define N_EDGE 600000
#define D 128
#define NNODE 50000
#define NE4 (N_EDGE / 4)

// ---- scratch (__device__ globals) ----
__device__ int g_cnt[3][NNODE];        // zeroed by scan after use (invariant: 0 at entry)
__device__ int g_off[3][NNODE + 1];
__device__ int g_pos[3][N_EDGE];       // per-edge within-node slot (from hist atomicAdd)
__device__ int g_esrc[3][N_EDGE + 8];  // CSR src arrays (padded)
// fp16 feature cache: row = 128 halves = 32 uint2
__device__ uint2 g_fu_h[N_USER * (D / 4)];
__device__ uint2 g_fi_h[N_ITEM * (D / 4)];
// fp16 aggregated means: [0]=uu, [1]=ub, [2]=iu
__device__ uint2 g_agg[3][NNODE * (D / 4)];
// fp16 TRANSPOSED weights: Wt[n*128 + k] = W[k*128 + n]; [0]=W_uu, [1]=W_iu, [2]=W_ub
__device__ __half g_Wt[3][D * D];

// ---------------------------------------------------------------------------
// prep: fp32->fp16 features + fp16 transposed weights (runs on side stream,
// concurrent with the CSR-build chain).
__global__ void prep_kernel(const float4* __restrict__ fu, const float4* __restrict__ fi,
                            const float* __restrict__ Wuu, const float* __restrict__ Wiu,
                            const float* __restrict__ Wub) {
    int i = blockIdx.x * blockDim.x + threadIdx.x;
    const int nv = N_USER * (D / 4);
    if (i < nv) {
        float4 v = fu[i];
        __half2 h0 = __floats2half2_rn(v.x, v.y);
        __half2 h1 = __floats2half2_rn(v.z, v.w);
        uint2 o; o.x = *(unsigned*)&h0; o.y = *(unsigned*)&h1;
        g_fu_h[i] = o;
    } else if (i < 2 * nv) {
        float4 v = fi[i - nv];
        __half2 h0 = __floats2half2_rn(v.x, v.y);
        __half2 h1 = __floats2half2_rn(v.z, v.w);
        uint2 o; o.x = *(unsigned*)&h0; o.y = *(unsigned*)&h1;
        g_fi_h[i - nv] = o;
    }
    if (i < 3 * D * D) {
        int m = i >> 14;
        int r = i & (D * D - 1);
        int n = r >> 7;
        int k = r & 127;
        const float* W = (m == 0) ? Wuu : (m == 1) ? Wiu : Wub;
        g_Wt[m][(n << 7) + k] = __float2half(W[(k << 7) + n]);
    }
}

// hist phase: count in-degrees AND record each edge's slot within its node.
__global__ void hist_kernel(const int* __restrict__ duu, const int* __restrict__ dub,
                            const int* __restrict__ diu) {
    unsigned t = blockIdx.x * blockDim.x + threadIdx.x;
    if (t >= 3u * NE4) return;
    int type = t / NE4;
    unsigned e4 = t - (unsigned)type * NE4;
    const int* dst = (type == 0) ? duu : (type == 1) ? dub : diu;
    int4 d = ((const int4*)dst)[e4];
    int* c = g_cnt[type];
    int4 p;
    p.x = atomicAdd(c + d.x, 1);
    p.y = atomicAdd(c + d.y, 1);
    p.z = atomicAdd(c + d.z, 1);
    p.w = atomicAdd(c + d.w, 1);
    ((int4*)g_pos[type])[e4] = p;
}

// exclusive scan per relation; re-zeroes g_cnt for the next invocation.
__global__ void scan_kernel() {
    const int type = blockIdx.x;
    const int t = threadIdx.x;
    const int lane = t & 31;
    const int wid = t >> 5;
    __shared__ int warp_sums[32];
    __shared__ int s_carry;
    if (t == 0) { s_carry = 0; g_off[type][0] = 0; }
    __syncthreads();

    for (int base = 0; base < NNODE; base += 1024) {
        int idx = base + t;
        int v = 0;
        if (idx < NNODE) {
            v = g_cnt[type][idx];
            g_cnt[type][idx] = 0;
        }
        int x = v;
#pragma unroll
        for (int o = 1; o < 32; o <<= 1) {
            int y = __shfl_up_sync(0xffffffffu, x, o);
            if (lane >= o) x += y;
        }
        if (lane == 31) warp_sums[wid] = x;
        __syncthreads();
        if (wid == 0) {
            int w = warp_sums[lane];
            int xs = w;
#pragma unroll
            for (int o = 1; o < 32; o <<= 1) {
                int y = __shfl_up_sync(0xffffffffu, xs, o);
                if (lane >= o) xs += y;
            }
            warp_sums[lane] = xs - w;
        }
        __syncthreads();
        int incl = x + warp_sums[wid];
        int carry = s_carry;
        if (idx < NNODE) g_off[type][idx + 1] = carry + incl;
        __syncthreads();
        if (t == 1023) s_carry = carry + incl;
        __syncthreads();
    }
}

// fill phase 2: ATOMIC-FREE scatter of src indices into CSR slots.
__global__ void fill_kernel(const int* __restrict__ suu, const int* __restrict__ duu,
                            const int* __restrict__ sub, const int* __restrict__ dub,
                            const int* __restrict__ siu, const int* __restrict__ diu) {
    unsigned t = blockIdx.x * blockDim.x + threadIdx.x;
    if (t >= 3u * NE4) return;
    int type = t / NE4;
    unsigned e4 = t - (unsigned)type * NE4;
    const int* src = (type == 0) ? suu : (type == 1) ? sub : siu;
    const int* dst = (type == 0) ? duu : (type == 1) ? dub : diu;
    int4 s = ((const int4*)src)[e4];
    int4 d = ((const int4*)dst)[e4];
    int4 p = ((const int4*)g_pos[type])[e4];
    const int* off = g_off[type];
    int* es = g_esrc[type];
    es[off[d.x] + p.x] = s.x;
    es[off[d.y] + p.y] = s.y;
    es[off[d.z] + p.z] = s.z;
    es[off[d.w] + p.w] = s.w;
}

// warp per (relation, dst-node): fp16 gather; depth-2 HADD2 tree over each
// 4-edge group, single convert, fp32 accumulate across groups; fp16 mean out.
__global__ void gather_kernel() {
    unsigned t = blockIdx.x * blockDim.x + threadIdx.x;
    unsigned gw = t >> 5;
    int lane = threadIdx.x & 31;
    if (gw >= 3u * NNODE) return;
    int type = gw / NNODE;
    int node = gw - type * NNODE;

    const uint2* fl = ((type == 2) ? g_fi_h : g_fu_h) + lane;  // lane base pointer
    const int* es = g_esrc[type];

    int start = g_off[type][node];
    int end = g_off[type][node + 1];
    int deg = end - start;

    float4 a = make_float4(0.f, 0.f, 0.f, 0.f);
    for (int e = start; e < end; e += 4) {
        int n = end - e;
        uint2 r[4];
#pragma unroll
        for (int u = 0; u < 4; u++) {
            r[u].x = 0u; r[u].y = 0u;                      // +0 is exact in fp16
            if (u < n) r[u] = fl[(unsigned)es[e + u] << 5];
        }
        // depth-2 fp16 tree per component, then one convert + fp32 accumulate
        __half2 tx = __hadd2(__hadd2(*(__half2*)&r[0].x, *(__half2*)&r[1].x),
                             __hadd2(*(__half2*)&r[2].x, *(__half2*)&r[3].x));
        __half2 ty = __hadd2(__hadd2(*(__half2*)&r[0].y, *(__half2*)&r[1].y),
                             __hadd2(*(__half2*)&r[2].y, *(__half2*)&r[3].y));
        float2 f0 = __half22float2(tx);
        float2 f1 = __half22float2(ty);
        a.x += f0.x; a.y += f0.y; a.z += f1.x; a.w += f1.y;
    }
    float inv = 1.0f / (float)(deg > 1 ? deg : 1);
    __half2 h0 = __floats2half2_rn(a.x * inv, a.y * inv);
    __half2 h1 = __floats2half2_rn(a.z * inv, a.w * inv);
    uint2 o; o.x = *(unsigned*)&h0; o.y = *(unsigned*)&h1;
    g_agg[type][(unsigned)node * 32u + (unsigned)lane] = o;
}

// ---------------------------------------------------------------------------
// HMMA GEMM (unchanged — verified correct).
__global__ void gemm_hmma_kernel(const float* __restrict__ b_uu,
                                 const float* __restrict__ b_iu,
                                 const float* __restrict__ b_ub,
                                 float* __restrict__ out, int BU) {
    __shared__ __align__(16) __half sA[64 * 128];
    __shared__ __align__(16) __half sB[128 * 128];

    int mode, bx;
    if ((int)blockIdx.x < BU) { mode = 0; bx = blockIdx.x; }
    else { mode = 1; bx = blockIdx.x - BU; }
    const int m0 = bx * 64;

    const int tid = threadIdx.x;
    const int wid = tid >> 5;
    const int lane = tid & 31;
    const int g = lane >> 2;
    const int tq = lane & 3;
    const int wr = (wid & 1) * 32;
    const int wc = (wid >> 1) * 32;

    float dacc[2][4][4];
#pragma unroll
    for (int mt = 0; mt < 2; mt++)
#pragma unroll
        for (int nt = 0; nt < 4; nt++)
#pragma unroll
            for (int q = 0; q < 4; q++) dacc[mt][nt][q] = 0.f;

    const int nsrc = (mode == 0) ? 2 : 1;
    for (int s = 0; s < nsrc; s++) {
        const uint2* A = (mode == 0) ? (s ? g_agg[2] : g_agg[0]) : g_agg[1];
        const __half* Wt = (mode == 0) ? (s ? g_Wt[1] : g_Wt[0]) : g_Wt[2];

        if (s) __syncthreads();
#pragma unroll
        for (int it = 0; it < 4; it++) {
            int idx = it * 256 + tid;
            int r = idx >> 4;
            int c16 = idx & 15;
            int grow = m0 + r;
            uint4 v = make_uint4(0u, 0u, 0u, 0u);
            if (grow < NNODE) v = ((const uint4*)(A + (size_t)grow * 32))[c16];
            *(uint4*)((char*)sA + r * 256 + ((c16 ^ (r & 7)) * 16)) = v;
        }
#pragma unroll
        for (int it = 0; it < 8; it++) {
            int idx = it * 256 + tid;
            int r = idx >> 4;
            int c16 = idx & 15;
            uint4 v = ((const uint4*)Wt)[idx];
            *(uint4*)((char*)sB + r * 256 + ((c16 ^ (r & 7)) * 16)) = v;
        }
        __syncthreads();

#pragma unroll
        for (int ks = 0; ks < 8; ks++) {
            const int k0 = ks * 16;
            unsigned a[2][4];
#pragma unroll
            for (int mt = 0; mt < 2; mt++) {
                int r0 = wr + mt * 16 + g;
                int r1 = r0 + 8;
                int w0 = (k0 >> 1) + tq;
                int w1 = w0 + 4;
                a[mt][0] = *(unsigned*)((char*)sA + r0 * 256 + ((w0 ^ ((r0 & 7) << 2)) << 2));
                a[mt][1] = *(unsigned*)((char*)sA + r1 * 256 + ((w0 ^ ((r1 & 7) << 2)) << 2));
                a[mt][2] = *(unsigned*)((char*)sA + r0 * 256 + ((w1 ^ ((r0 & 7) << 2)) << 2));
                a[mt][3] = *(unsigned*)((char*)sA + r1 * 256 + ((w1 ^ ((r1 & 7) << 2)) << 2));
            }
#pragma unroll
            for (int nt = 0; nt < 4; nt++) {
                int n = wc + nt * 8 + g;
                int w0 = (k0 >> 1) + tq;
                int w1 = w0 + 4;
                unsigned b0 = *(unsigned*)((char*)sB + n * 256 + ((w0 ^ ((n & 7) << 2)) << 2));
                unsigned b1 = *(unsigned*)((char*)sB + n * 256 + ((w1 ^ ((n & 7) << 2)) << 2));
#pragma unroll
                for (int mt = 0; mt < 2; mt++) {
                    asm volatile(
                        "mma.sync.aligned.m16n8k16.row.col.f32.f16.f16.f32 "
                        "{%0,%1,%2,%3}, {%4,%5,%6,%7}, {%8,%9}, {%0,%1,%2,%3};"
                        : "+f"(dacc[mt][nt][0]), "+f"(dacc[mt][nt][1]),
                          "+f"(dacc[mt][nt][2]), "+f"(dacc[mt][nt][3])
                        : "r"(a[mt][0]), "r"(a[mt][1]), "r"(a[mt][2]), "r"(a[mt][3]),
                          "r"(b0), "r"(b1));
                }
            }
        }
    }

    float* outp = (mode == 0) ? out : out + (size_t)N_USER * D;
    const float* bias1 = (mode == 0) ? b_uu : b_ub;
    const int* off1 = (mode == 0) ? g_off[0] : g_off[1];
    const int* off2 = g_off[2];

    float2 bv1[4], bv2[4];
#pragma unroll
    for (int nt = 0; nt < 4; nt++) {
        int col = wc + nt * 8 + tq * 2;
        bv1[nt] = *(const float2*)(bias1 + col);
        bv2[nt] = (mode == 0) ? *(const float2*)(b_iu + col) : make_float2(0.f, 0.f);
    }

#pragma unroll
    for (int mt = 0; mt < 2; mt++) {
#pragma unroll
        for (int half_m = 0; half_m < 2; half_m++) {
            int row = m0 + wr + mt * 16 + half_m * 8 + g;
            if (row >= NNODE) continue;
            bool m1 = off1[row + 1] > off1[row];
            bool m2 = (mode == 0) && (off2[row + 1] > off2[row]);
#pragma unroll
            for (int nt = 0; nt < 4; nt++) {
                int col = wc + nt * 8 + tq * 2;
                float2 v;
                v.x = dacc[mt][nt][half_m * 2 + 0];
                v.y = dacc[mt][nt][half_m * 2 + 1];
                if (m1) { v.x += bv1[nt].x; v.y += bv1[nt].y; }
                if (m2) { v.x += bv2[nt].x; v.y += bv2[nt].y; }
                *(float2*)(outp + (size_t)row * D + col) = v;
            }
        }
    }
}

extern "C" void kernel_launch(void* const* d_in, const int* in_sizes, int n_in,
                              void* d_out, int out_size) {
    const float* feat_user = (const float*)d_in[0];
    const float* feat_item = (const float*)d_in[1];
    const float* W_uu = (const float*)d_in[2];
    const float* b_uu = (const float*)d_in[3];
    const float* W_ub = (const float*)d_in[4];
    const float* b_ub = (const float*)d_in[5];
    const float* W_iu = (const float*)d_in[6];
    const float* b_iu = (const float*)d_in[7];
    const int* src_uu = (const int*)d_in[8];
    const int* dst_uu = (const int*)d_in[9];
    const int* src_ub = (const int*)d_in[10];
    const int* dst_ub = (const int*)d_in[11];
    const int* src_iu = (const int*)d_in[12];
    const int* dst_iu = (const int*)d_in[13];
    float* out = (float*)d_out;

    // one-time host-side stream/event setup (host caching only; per-call GPU
    // work is identical every call, so graph capture stays deterministic)
    static cudaStream_t s2 = nullptr;
    static cudaEvent_t e_root = nullptr, e_prep = nullptr;
    if (!s2) {
        cudaStreamCreate(&s2);
        cudaEventCreateWithFlags(&e_root, cudaEventDisableTiming);
        cudaEventCreateWithFlags(&e_prep, cudaEventDisableTiming);
    }

    // fork: prep (fp16 conversions) concurrent with CSR build
    cudaEventRecord(e_root, 0);
    cudaStreamWaitEvent(s2, e_root, 0);
    int prep_threads = 2 * N_USER * (D / 4);
    prep_kernel<<<(prep_threads + 255) / 256, 256, 0, s2>>>(
        (const float4*)feat_user, (const float4*)feat_item, W_uu, W_iu, W_ub);
    cudaEventRecord(e_prep, s2);

    // main stream: CSR build (hist records slots -> scan -> atomic-free fill)
    hist_kernel<<<(3 * NE4 + 255) / 256, 256>>>(dst_uu, dst_ub, dst_iu);
    scan_kernel<<<3, 1024>>>();
    fill_kernel<<<(3 * NE4 + 255) / 256, 256>>>(src_uu, dst_uu, src_ub, dst_ub,
                                                src_iu, dst_iu);

    // join: gather needs prep (features) and fill (CSR)
    cudaStreamWaitEvent(0, e_prep, 0);
    unsigned gthreads = 3u * NNODE * 32u;
    gather_kernel<<<(gthreads + 255) / 256, 256>>>();

    int BU = (N_USER + 63) / 64;
    int BI = (N_ITEM + 63) / 64;
    gemm_hmma_kernel<<<BU + BI, 256>>>(b_uu, b_iu, b_ub, out, BU);
}